// round 7
// baseline (speedup 1.0000x reference)
#include <cuda_runtime.h>
#include <cstdint>

#define BB 16
#define NN 8192
#define HH 128
#define GG 10
#define DCC 16
#define NBLK 6
#define K1 154        // H + G + DC (local cat width)
#define KPROJ0 272    // 2H + DC
#define KBLK 282      // 2H + G + DC
#define CATS 132      // padded cat row stride (floats)
#define W1S 155       // padded l1w row stride
#define W2S 129       // padded l2w row stride
#define HTS 65        // h_l staging row stride (float2 units)

// SMEM layout for the local kernel (float offsets)
#define SM_CAT 0
#define SM_BUF (K1*CATS)                 // 20328 : w1 (128x155) then reused as hT (128x65 f2)
#define SM_W2  (SM_BUF + HH*W1S)         // 40168 : w2 (128x129)
#define SM_B1  (SM_W2 + HH*W2S)          // 56680
#define SM_B2  (SM_B1 + HH)
#define SM_M   (SM_B2 + HH)
#define SM_OW  (SM_M + HH)
#define SM_OB  (SM_OW + 3*HH)
#define SM_TOT (SM_OB + 4)               // 57452 floats = 229808 bytes

typedef unsigned long long u64;

// persistent scratch (allocation-free rule: __device__ globals)
__device__ float g_xl[(size_t)BB * HH * NN];      // 64 MB, layout (B, H, N)
__device__ float g_part[BB * 64 * HH];            // per-tile pooling partials from local kernel
__device__ float g_part0[BB * 16 * HH];           // partials from projection kernel
__device__ float g_cnt0[BB * 16];
__device__ float g_cnt[BB];
__device__ float g_xg[BB * GG];

__device__ __forceinline__ float lrelu(float v) { return fmaxf(v, 0.01f * v); }

__device__ __forceinline__ u64 pk2(float x, float y) {
    u64 r; asm("mov.b64 %0, {%1,%2};" : "=l"(r) : "f"(x), "f"(y)); return r;
}
__device__ __forceinline__ void upk2(u64 v, float& x, float& y) {
    asm("mov.b64 {%0,%1}, %2;" : "=f"(x), "=f"(y) : "l"(v));
}
__device__ __forceinline__ void fma2(u64& d, u64 a, u64 b) {
    asm("fma.rn.f32x2 %0, %1, %2, %0;" : "+l"(d) : "l"(a), "l"(b));
}

// ---------------------------------------------------------------------------
// K0: xl0 = lrelu(x_local @ proj_lw^T + proj_lb) * mask, stored (B,H,N),
//     plus per-CTA pooling partial sums and mask counts.
// grid (16 b, 16 tiles), 256 threads, 512 points per CTA.
// ---------------------------------------------------------------------------
__global__ __launch_bounds__(256) void k_proj_local(
    const float* __restrict__ x, const float* __restrict__ mask,
    const float* __restrict__ lw, const float* __restrict__ lb)
{
    __shared__ float sw[HH * 3], sb[HH], sp[8][HH], sc[8];
    int b = blockIdx.x, tile = blockIdx.y, tid = threadIdx.x;
    int p0 = tile * 512;
    for (int i = tid; i < HH * 3; i += 256) sw[i] = lw[i];
    for (int i = tid; i < HH; i += 256) sb[i] = lb[i];
    for (int i = tid; i < 8 * HH; i += 256) ((float*)sp)[i] = 0.f;
    __syncthreads();

    int w = tid >> 5, ln = tid & 31;
    float cacc = 0.f;
    for (int gI = 0; gI < 2; ++gI) {
        int p = p0 + w * 64 + gI * 32 + ln;
        const float* xr = x + ((size_t)b * NN + p) * 3;
        float x0 = xr[0], x1 = xr[1], x2 = xr[2];
        float m = mask[(size_t)b * NN + p];
        cacc += m;
        float* orow = g_xl + (size_t)b * HH * NN + p;
        for (int h = 0; h < HH; ++h) {
            float v = fmaf(x0, sw[h * 3], fmaf(x1, sw[h * 3 + 1], fmaf(x2, sw[h * 3 + 2], sb[h])));
            v = lrelu(v) * m;
            orow[(size_t)h * NN] = v;
            float r = v;
            #pragma unroll
            for (int off = 16; off; off >>= 1) r += __shfl_xor_sync(0xffffffffu, r, off);
            if (ln == 0) sp[w][h] += r;
        }
    }
    #pragma unroll
    for (int off = 16; off; off >>= 1) cacc += __shfl_xor_sync(0xffffffffu, cacc, off);
    if (ln == 0) sc[w] = cacc;
    __syncthreads();
    if (tid < HH) {
        float s = 0.f;
        #pragma unroll
        for (int i = 0; i < 8; ++i) s += sp[i][tid];
        g_part0[(b * 16 + tile) * HH + tid] = s;
    }
    if (tid == 0) {
        float c = 0.f;
        for (int i = 0; i < 8; ++i) c += sc[i];
        g_cnt0[b * 16 + tile] = c;
    }
}

// ---------------------------------------------------------------------------
// KG: global path. phase==0: reduce K0 partials, run 3-layer projection
//     global MLP, then EPiC block-0 global. phase==1: reduce local-kernel
//     partials and run EPiC block-`blk` global. grid 16 (b), 128 threads.
// ---------------------------------------------------------------------------
__device__ __forceinline__ float dot_g(const float* __restrict__ w,
                                       const float* __restrict__ xs, int n) {
    float a0 = 0.f, a1 = 0.f, a2 = 0.f, a3 = 0.f;
    int k = 0;
    for (; k + 4 <= n; k += 4) {
        a0 = fmaf(w[k],     xs[k],     a0);
        a1 = fmaf(w[k + 1], xs[k + 1], a1);
        a2 = fmaf(w[k + 2], xs[k + 2], a2);
        a3 = fmaf(w[k + 3], xs[k + 3], a3);
    }
    for (; k < n; ++k) a0 = fmaf(w[k], xs[k], a0);
    return (a0 + a1) + (a2 + a3);
}

__global__ __launch_bounds__(128) void k_global(
    int phase, int blk, const float* __restrict__ ctx,
    const float* __restrict__ pg0w, const float* __restrict__ pg0b,
    const float* __restrict__ pg1w, const float* __restrict__ pg1b,
    const float* __restrict__ pg2w, const float* __restrict__ pg2b,
    const float* __restrict__ g1w, const float* __restrict__ g1b,
    const float* __restrict__ g2w, const float* __restrict__ g2b)
{
    __shared__ float sp[KBLK + 6];
    __shared__ float sh[HH];
    __shared__ float sxg[GG];
    __shared__ float scn;
    int b = blockIdx.x, j = threadIdx.x;

    float s = 0.f;
    if (phase == 0) {
        for (int c = 0; c < 16; ++c) s += g_part0[(b * 16 + c) * HH + j];
        if (j == 0) {
            float cc = 0.f;
            for (int c = 0; c < 16; ++c) cc += g_cnt0[b * 16 + c];
            scn = cc; g_cnt[b] = cc;
        }
    } else {
        for (int c = 0; c < 64; ++c) s += g_part[(b * 64 + c) * HH + j];
        if (j == 0) scn = g_cnt[b];
    }
    __syncthreads();
    float cnt = scn;
    sp[j] = s / cnt;
    sp[HH + j] = s;

    if (phase == 0) {
        if (j < DCC) sp[2 * HH + j] = ctx[b * DCC + j];
        __syncthreads();
        float a = lrelu(dot_g(pg0w + (size_t)j * KPROJ0, sp, KPROJ0) + pg0b[j]);
        __syncthreads();
        sh[j] = a; __syncthreads();
        float a2 = lrelu(dot_g(pg1w + (size_t)j * HH, sh, HH) + pg1b[j]);
        __syncthreads();
        sh[j] = a2; __syncthreads();
        if (j < GG) sxg[j] = lrelu(dot_g(pg2w + (size_t)j * HH, sh, HH) + pg2b[j]);
        __syncthreads();
    } else {
        if (j < GG) sxg[j] = g_xg[b * GG + j];
        __syncthreads();
    }

    // EPiC block `blk` global path: pooled = [mean, sum, xg, ctx]
    if (j < GG)  sp[2 * HH + j] = sxg[j];
    if (j < DCC) sp[2 * HH + GG + j] = ctx[b * DCC + j];
    __syncthreads();
    float hg = lrelu(dot_g(g1w + ((size_t)blk * HH + j) * KBLK, sp, KBLK) + g1b[blk * HH + j]);
    __syncthreads();
    sh[j] = hg; __syncthreads();
    if (j < GG) {
        float a = dot_g(g2w + ((size_t)blk * GG + j) * HH, sh, HH) + g2b[blk * GG + j];
        g_xg[b * GG + j] = lrelu(a + sxg[j]);
    }
}

// ---------------------------------------------------------------------------
// L: per-point two-layer MLP with residual (the heavy kernel).
//    128-point tile per CTA. cat (154x128) and both weight matrices in SMEM.
//    fma.rn.f32x2 packed-fp32 GEMM: each thread owns 8 outputs x 4 point-pairs.
//    Epilogue: residual + lrelu + mask, fused pooling partials, coalesced
//    write-back. Last block computes the output head directly into d_out.
// grid (64 tiles, 16 b), 256 threads, 1 CTA/SM.
// ---------------------------------------------------------------------------
extern __shared__ float smem[];

__global__ void __launch_bounds__(256, 1) k_local(
    int blk, int last,
    const float* __restrict__ l1w, const float* __restrict__ l1b,
    const float* __restrict__ l2w, const float* __restrict__ l2b,
    const float* __restrict__ ctx, const float* __restrict__ mask,
    const float* __restrict__ outw, const float* __restrict__ outb,
    float* __restrict__ dout)
{
    float* s_cat = smem + SM_CAT;
    float* s_buf = smem + SM_BUF;
    float* s_w2  = smem + SM_W2;
    float* s_b1  = smem + SM_B1;
    float* s_b2  = smem + SM_B2;
    float* s_m   = smem + SM_M;
    float* s_ow  = smem + SM_OW;
    float* s_ob  = smem + SM_OB;

    int tile = blockIdx.x, b = blockIdx.y, tid = threadIdx.x;
    int p0 = tile * 128;
    int tj = tid & 15, tp = tid >> 4;

    // ---- loads ----
    {
        const float* xbase = g_xl + (size_t)b * HH * NN + p0;
        for (int idx = tid; idx < HH * 32; idx += 256) {       // xl tile (k-major, point-contiguous)
            int r = idx >> 5, q = idx & 31;
            float4 v = *(const float4*)(xbase + (size_t)r * NN + q * 4);
            *(float4*)(s_cat + r * CATS + q * 4) = v;
        }
        for (int idx = tid; idx < GG * 128; idx += 256) {      // xg rows (broadcast per point)
            int r = idx >> 7, q = idx & 127;
            s_cat[(HH + r) * CATS + q] = g_xg[b * GG + r];
        }
        for (int idx = tid; idx < DCC * 128; idx += 256) {     // ctx rows
            int r = idx >> 7, q = idx & 127;
            s_cat[(HH + GG + r) * CATS + q] = ctx[b * DCC + r];
        }
        const float* w1g = l1w + (size_t)blk * HH * K1;
        for (int idx = tid; idx < HH * K1; idx += 256) {
            int r = idx / K1, c = idx - r * K1;
            s_buf[r * W1S + c] = w1g[idx];
        }
        const float* w2g = l2w + (size_t)blk * HH * HH;
        for (int idx = tid; idx < HH * HH; idx += 256) {
            int r = idx >> 7, c = idx & 127;
            s_w2[r * W2S + c] = w2g[idx];
        }
        if (tid < HH) {
            s_b1[tid] = l1b[blk * HH + tid];
            s_b2[tid] = l2b[blk * HH + tid];
            s_m[tid]  = mask[(size_t)b * NN + p0 + tid];
        }
        if (last) {
            for (int idx = tid; idx < 3 * HH; idx += 256) s_ow[idx] = outw[idx];
            if (tid < 3) s_ob[tid] = outb[tid];
        }
    }
    __syncthreads();

    u64 acc[8][4];

    // ---- stage 1: h_l = lrelu(W1 @ cat + b1) ----
    #pragma unroll
    for (int j = 0; j < 8; ++j)
        #pragma unroll
        for (int i = 0; i < 4; ++i) acc[j][i] = 0ull;

    #pragma unroll 2
    for (int k = 0; k < K1; ++k) {
        u64 a[4];
        #pragma unroll
        for (int i = 0; i < 4; ++i)
            a[i] = *(const u64*)(s_cat + k * CATS + 2 * (tp + 16 * i));
        #pragma unroll
        for (int j = 0; j < 8; ++j) {
            float wv = s_buf[(tj + 16 * j) * W1S + k];
            u64 wd = pk2(wv, wv);
            #pragma unroll
            for (int i = 0; i < 4; ++i) fma2(acc[j][i], a[i], wd);
        }
    }
    #pragma unroll
    for (int j = 0; j < 8; ++j) {
        float bb = s_b1[tj + 16 * j];
        #pragma unroll
        for (int i = 0; i < 4; ++i) {
            float x, y; upk2(acc[j][i], x, y);
            x = lrelu(x + bb); y = lrelu(y + bb);
            acc[j][i] = pk2(x, y);
        }
    }
    __syncthreads();   // everyone done reading w1 before hT overwrites it
    #pragma unroll
    for (int j = 0; j < 8; ++j)
        #pragma unroll
        for (int i = 0; i < 4; ++i)
            *(u64*)(s_buf + ((tj + 16 * j) * HTS + (tp + 16 * i)) * 2) = acc[j][i];
    __syncthreads();

    // ---- stage 2: xl_new = lrelu(W2 @ h_l + b2 + xl) * mask ----
    #pragma unroll
    for (int j = 0; j < 8; ++j)
        #pragma unroll
        for (int i = 0; i < 4; ++i) acc[j][i] = 0ull;

    #pragma unroll 2
    for (int k = 0; k < HH; ++k) {
        u64 a[4];
        #pragma unroll
        for (int i = 0; i < 4; ++i)
            a[i] = *(const u64*)(s_buf + (k * HTS + (tp + 16 * i)) * 2);
        #pragma unroll
        for (int j = 0; j < 8; ++j) {
            float wv = s_w2[(tj + 16 * j) * W2S + k];
            u64 wd = pk2(wv, wv);
            #pragma unroll
            for (int i = 0; i < 4; ++i) fma2(acc[j][i], a[i], wd);
        }
    }
    #pragma unroll
    for (int j = 0; j < 8; ++j) {
        int jr = tj + 16 * j;
        float bb = s_b2[jr];
        #pragma unroll
        for (int i = 0; i < 4; ++i) {
            int pp = tp + 16 * i;
            float x, y; upk2(acc[j][i], x, y);
            float rx = s_cat[jr * CATS + 2 * pp];
            float ry = s_cat[jr * CATS + 2 * pp + 1];
            x = lrelu(x + bb + rx) * s_m[2 * pp];
            y = lrelu(y + bb + ry) * s_m[2 * pp + 1];
            acc[j][i] = pk2(x, y);
        }
    }
    __syncthreads();   // everyone done reading hT before xl_new overwrites it
    #pragma unroll
    for (int j = 0; j < 8; ++j)
        #pragma unroll
        for (int i = 0; i < 4; ++i)
            *(u64*)(s_buf + ((tj + 16 * j) * HTS + (tp + 16 * i)) * 2) = acc[j][i];
    __syncthreads();

    if (!last) {
        // coalesced write-back of xl_new + fused pooling partials
        float* xbase = g_xl + (size_t)b * HH * NN + p0;
        for (int idx = tid; idx < HH * 64; idx += 256) {
            int r = idx >> 6, q = idx & 63;
            *(float2*)(xbase + (size_t)r * NN + 2 * q) =
                *(const float2*)(s_buf + (r * HTS + q) * 2);
        }
        if (tid < HH) {
            const float* row = s_buf + tid * HTS * 2;
            float a0 = 0.f, a1 = 0.f, a2 = 0.f, a3 = 0.f;
            for (int q = 0; q < 128; q += 4) {
                a0 += row[q]; a1 += row[q + 1]; a2 += row[q + 2]; a3 += row[q + 3];
            }
            g_part[(b * 64 + tile) * HH + tid] = (a0 + a1) + (a2 + a3);
        }
    } else {
        // fused output head: out = mask * (xl_new @ outw^T + outb)
        if (tid < 128) {
            int p = tid;
            float m = s_m[p];
            float s0 = s_ob[0], s1 = s_ob[1], s2 = s_ob[2];
            for (int j = 0; j < HH; ++j) {
                float v = s_buf[j * HTS * 2 + p];
                s0 = fmaf(v, s_ow[j], s0);
                s1 = fmaf(v, s_ow[HH + j], s1);
                s2 = fmaf(v, s_ow[2 * HH + j], s2);
            }
            float* o = dout + ((size_t)b * NN + p0 + p) * 3;
            o[0] = m * s0; o[1] = m * s1; o[2] = m * s2;
        }
    }
}

// ---------------------------------------------------------------------------
extern "C" void kernel_launch(void* const* d_in, const int* in_sizes, int n_in,
                              void* d_out, int out_size)
{
    const float* x_local = (const float*)d_in[0];
    const float* context = (const float*)d_in[1];
    const float* mask    = (const float*)d_in[2];
    const float* proj_lw = (const float*)d_in[3];
    const float* proj_lb = (const float*)d_in[4];
    const float* pg0w    = (const float*)d_in[5];
    const float* pg0b    = (const float*)d_in[6];
    const float* pg1w    = (const float*)d_in[7];
    const float* pg1b    = (const float*)d_in[8];
    const float* pg2w    = (const float*)d_in[9];
    const float* pg2b    = (const float*)d_in[10];
    const float* g1w     = (const float*)d_in[11];
    const float* g1b     = (const float*)d_in[12];
    const float* g2w     = (const float*)d_in[13];
    const float* g2b     = (const float*)d_in[14];
    const float* l1w     = (const float*)d_in[15];
    const float* l1b     = (const float*)d_in[16];
    const float* l2w     = (const float*)d_in[17];
    const float* l2b     = (const float*)d_in[18];
    const float* outw    = (const float*)d_in[19];
    const float* outb    = (const float*)d_in[20];
    float* out = (float*)d_out;

    cudaFuncSetAttribute(k_local, cudaFuncAttributeMaxDynamicSharedMemorySize, SM_TOT * 4);

    k_proj_local<<<dim3(16, 16), 256>>>(x_local, mask, proj_lw, proj_lb);
    for (int blk = 0; blk < NBLK; ++blk) {
        k_global<<<16, 128>>>(blk == 0 ? 0 : 1, blk, context,
                              pg0w, pg0b, pg1w, pg1b, pg2w, pg2b,
                              g1w, g1b, g2w, g2b);
        k_local<<<dim3(64, 16), 256, SM_TOT * 4>>>(
            blk, blk == NBLK - 1 ? 1 : 0,
            l1w, l1b, l2w, l2b, context, mask, outw, outb, out);
    }
}

// round 9
// speedup vs baseline: 1.2991x; 1.2991x over previous
#include <cuda_runtime.h>
#include <cuda_bf16.h>
#include <cstdint>

#define BB 16
#define NN 8192
#define HH 128
#define GG 10
#define DCC 16
#define NBLK 6
#define K1 154          // H + G + DC
#define KPROJ0 272
#define KBLK 282
#define NP 128          // points per local CTA
#define NT 64           // local tiles per batch
#define NT0 32          // proj tiles per batch

// ---- k_local dynamic SMEM byte offsets ----
// phase A: A1 = W1 split (128 x 168 bf16, stride 336B), B1 = cat split (128 x 168)
// phase B (after stage-1 sync): B2 = h split (128 x 136, stride 272B) over A1,
//                               A2 = W2 split (128 x 136) over B1.
// last-block: fp32 staging [128][129] over B2 region.
#define SAB1 336
#define SAB2 272
#define O_A1H 0
#define O_A1L 43008
#define O_B1H 86016
#define O_B1L 129024
#define O_B2H 0
#define O_B2L 43008
#define O_A2H 86016
#define O_A2L 129024
#define O_STG 0
#define O_MB  172032
#define O_B1V (O_MB)
#define O_B2V (O_MB + 512)
#define O_MK  (O_MB + 1024)
#define O_OW  (O_MB + 1536)
#define O_OB  (O_MB + 3072)
#define SMEM_SZ 175232

typedef unsigned int u32;

// persistent scratch (allocation-free rule: __device__ globals)
__device__ float g_xl[(size_t)BB * HH * NN];      // (B, H, N)
__device__ float g_part[BB * NT * HH];
__device__ float g_part0[BB * NT0 * HH];
__device__ float g_cnt0[BB * NT0];
__device__ float g_cnt[BB];
__device__ float g_xg[BB * GG];

__device__ __forceinline__ float lrelu(float v) { return fmaxf(v, 0.01f * v); }

__device__ __forceinline__ u32 s2u(const void* p) {
    u32 a;
    asm("{ .reg .u64 t; cvta.to.shared.u64 t, %1; cvt.u32.u64 %0, t; }" : "=r"(a) : "l"(p));
    return a;
}
__device__ __forceinline__ void bsplit(float v, __nv_bfloat16& h, __nv_bfloat16& l) {
    h = __float2bfloat16(v);
    l = __float2bfloat16(v - __bfloat162float(h));
}

#define LDM4(r, addr) \
    asm volatile("ldmatrix.sync.aligned.m8n8.x4.shared.b16 {%0,%1,%2,%3}, [%4];" \
        : "=r"((r)[0]), "=r"((r)[1]), "=r"((r)[2]), "=r"((r)[3]) : "r"(addr))

#define MMA(c, a, b0_, b1_) \
    asm volatile("mma.sync.aligned.m16n8k16.row.col.f32.bf16.bf16.f32 " \
        "{%0,%1,%2,%3}, {%4,%5,%6,%7}, {%8,%9}, {%0,%1,%2,%3};" \
        : "+f"((c)[0]), "+f"((c)[1]), "+f"((c)[2]), "+f"((c)[3]) \
        : "r"((a)[0]), "r"((a)[1]), "r"((a)[2]), "r"((a)[3]), "r"(b0_), "r"(b1_))

// D[M=16/warp, N=128] += (split) A[., K] x B[N, K]^T.
// A: row-major (row m, contig k). B: rows n, contig k. Both SW-free padded strides.
template<int KST, int SAb, int SBb>
__device__ __forceinline__ void gemm_ss(u32 aH, u32 aL, u32 bH, u32 bL,
                                        int lane, int m_base, float* acc)
{
    u32 aOff = aH + (u32)(m_base + (lane & 15)) * SAb + ((lane & 16) ? 16u : 0u);
    u32 aOffL = aOff + (O_A1L - O_A1H) * 0 + (aL - aH);
    u32 bRow = (u32)((lane & 7) + ((lane & 16) >> 1));
    u32 bOff = bH + bRow * SBb + ((lane & 8) ? 16u : 0u);
    u32 bOffL = bOff + (bL - bH);
    #pragma unroll 2
    for (int ks = 0; ks < KST; ++ks) {
        u32 ak = (u32)ks * 32u;
        u32 ah[4], al[4];
        LDM4(ah, aOff + ak);
        LDM4(al, aOffL + ak);
        #pragma unroll
        for (int np = 0; np < 8; ++np) {
            u32 bk = (u32)(np * 16) * SBb + (u32)ks * 32u;
            u32 bh[4], bl[4];
            LDM4(bh, bOff + bk);
            LDM4(bl, bOffL + bk);
            float* c0 = acc + (2 * np) * 4;
            float* c1 = acc + (2 * np + 1) * 4;
            MMA(c0, ah, bh[0], bh[1]);
            MMA(c0, ah, bl[0], bl[1]);
            MMA(c0, al, bh[0], bh[1]);
            MMA(c1, ah, bh[2], bh[3]);
            MMA(c1, ah, bl[2], bl[3]);
            MMA(c1, al, bh[2], bh[3]);
        }
    }
}

// ---------------------------------------------------------------------------
// k_proj: xl0 = lrelu(x @ proj_lw^T + b) * mask into g_xl (B,H,N),
//         fused pooling partials + mask counts. grid (16, 32), 256 thr.
// ---------------------------------------------------------------------------
__global__ __launch_bounds__(256) void k_proj(
    const float* __restrict__ x, const float* __restrict__ mask,
    const float* __restrict__ lw, const float* __restrict__ lb)
{
    __shared__ float sw[HH * 3], sbv[HH], st[32][257], sp[HH], sc[8];
    int b = blockIdx.x, tile = blockIdx.y, tid = threadIdx.x;
    int wid = tid >> 5, lid = tid & 31;
    int p0 = tile * 256, p = p0 + tid;
    for (int i = tid; i < HH * 3; i += 256) sw[i] = lw[i];
    for (int i = tid; i < HH; i += 256) { sbv[i] = lb[i]; sp[i] = 0.f; }
    __syncthreads();
    const float* xr = x + ((size_t)b * NN + p) * 3;
    float x0 = xr[0], x1 = xr[1], x2 = xr[2];
    float m = mask[(size_t)b * NN + p];
    float cacc = m;
    #pragma unroll
    for (int o = 16; o; o >>= 1) cacc += __shfl_xor_sync(0xffffffffu, cacc, o);
    if (lid == 0) sc[wid] = cacc;

    for (int hc = 0; hc < 4; ++hc) {
        #pragma unroll
        for (int r = 0; r < 32; ++r) {
            int h = hc * 32 + r;
            float v = fmaf(x0, sw[h * 3], fmaf(x1, sw[h * 3 + 1], fmaf(x2, sw[h * 3 + 2], sbv[h])));
            st[r][tid] = lrelu(v) * m;
        }
        __syncthreads();
        for (int idx = tid; idx < 32 * 256; idx += 256) {
            int r = idx >> 8, q = idx & 255;
            g_xl[(size_t)b * HH * NN + (size_t)(hc * 32 + r) * NN + p0 + q] = st[r][q];
        }
        #pragma unroll
        for (int rr = 0; rr < 4; ++rr) {
            int r = wid * 4 + rr;
            float a = 0.f;
            #pragma unroll
            for (int q = 0; q < 8; ++q) a += st[r][lid + q * 32];
            #pragma unroll
            for (int o = 16; o; o >>= 1) a += __shfl_xor_sync(0xffffffffu, a, o);
            if (lid == 0) sp[hc * 32 + r] += a;
        }
        __syncthreads();
    }
    if (tid < HH) g_part0[(b * NT0 + tile) * HH + tid] = sp[tid];
    if (tid == 0) {
        float c = 0.f;
        #pragma unroll
        for (int i = 0; i < 8; ++i) c += sc[i];
        g_cnt0[b * NT0 + tile] = c;
    }
}

// ---------------------------------------------------------------------------
// k_global: warp-per-output dots (coalesced weight reads). grid 16, 128 thr.
// ---------------------------------------------------------------------------
__device__ __forceinline__ float dotw(const float* __restrict__ w,
                                      const float* __restrict__ xs, int n, int lid) {
    float a = 0.f;
    for (int k = lid; k < n; k += 32) a = fmaf(w[k], xs[k], a);
    #pragma unroll
    for (int o = 16; o; o >>= 1) a += __shfl_xor_sync(0xffffffffu, a, o);
    return a;
}

__global__ __launch_bounds__(128) void k_global(
    int phase, int blk, const float* __restrict__ ctx,
    const float* __restrict__ pg0w, const float* __restrict__ pg0b,
    const float* __restrict__ pg1w, const float* __restrict__ pg1b,
    const float* __restrict__ pg2w, const float* __restrict__ pg2b,
    const float* __restrict__ g1w, const float* __restrict__ g1b,
    const float* __restrict__ g2w, const float* __restrict__ g2b)
{
    __shared__ float sp[KBLK], spP[KPROJ0], sh[HH], sh2[HH], sxg[GG];
    __shared__ float scn;
    int b = blockIdx.x, j = threadIdx.x, wid = j >> 5, lid = j & 31;

    float s = 0.f;
    if (phase == 0) {
        #pragma unroll 4
        for (int c = 0; c < NT0; ++c) s += g_part0[(b * NT0 + c) * HH + j];
        if (j == 0) {
            float cc = 0.f;
            for (int c = 0; c < NT0; ++c) cc += g_cnt0[b * NT0 + c];
            scn = cc; g_cnt[b] = cc;
        }
    } else {
        #pragma unroll 4
        for (int c = 0; c < NT; ++c) s += g_part[(b * NT + c) * HH + j];
        if (j == 0) scn = g_cnt[b];
    }
    __syncthreads();
    float cnt = scn;
    sp[j] = s / cnt; sp[HH + j] = s;
    if (phase == 0) {
        spP[j] = s / cnt; spP[HH + j] = s;
        if (j < DCC) spP[2 * HH + j] = ctx[b * DCC + j];
    }
    if (j < DCC) sp[2 * HH + GG + j] = ctx[b * DCC + j];
    __syncthreads();

    if (phase == 0) {
        for (int o = wid; o < HH; o += 4) {
            float a = dotw(pg0w + (size_t)o * KPROJ0, spP, KPROJ0, lid);
            if (lid == 0) sh[o] = lrelu(a + pg0b[o]);
        }
        __syncthreads();
        for (int o = wid; o < HH; o += 4) {
            float a = dotw(pg1w + (size_t)o * HH, sh, HH, lid);
            if (lid == 0) sh2[o] = lrelu(a + pg1b[o]);
        }
        __syncthreads();
        for (int o = wid; o < GG; o += 4) {
            float a = dotw(pg2w + (size_t)o * HH, sh2, HH, lid);
            if (lid == 0) sxg[o] = lrelu(a + pg2b[o]);
        }
        __syncthreads();
    } else {
        if (j < GG) sxg[j] = g_xg[b * GG + j];
        __syncthreads();
    }

    if (j < GG) sp[2 * HH + j] = sxg[j];
    __syncthreads();
    for (int o = wid; o < HH; o += 4) {
        float a = dotw(g1w + ((size_t)blk * HH + o) * KBLK, sp, KBLK, lid);
        if (lid == 0) sh[o] = lrelu(a + g1b[blk * HH + o]);
    }
    __syncthreads();
    for (int o = wid; o < GG; o += 4) {
        float a = dotw(g2w + ((size_t)blk * GG + o) * HH, sh, HH, lid) + g2b[blk * GG + o];
        if (lid == 0) g_xg[b * GG + o] = lrelu(a + sxg[o]);
    }
}

// ---------------------------------------------------------------------------
// k_local: mma.sync bf16-split two-layer MLP + residual + pooling partials.
// grid (64 tiles, 16 b), 256 threads (8 warps x 16 M-rows), 128 points/CTA.
// ---------------------------------------------------------------------------
extern __shared__ char smem[];

__global__ void __launch_bounds__(256, 1) k_local(
    int blk, int last,
    const float* __restrict__ l1w, const float* __restrict__ l1b,
    const float* __restrict__ l2w, const float* __restrict__ l2b,
    const float* __restrict__ ctx, const float* __restrict__ mask,
    const float* __restrict__ outw, const float* __restrict__ outb,
    float* __restrict__ dout)
{
    char* sm = smem;
    u32 sb = s2u(sm);
    int tile = blockIdx.x, b = blockIdx.y, tid = threadIdx.x;
    int wid = tid >> 5, lane = tid & 31;
    int p0 = tile * NP;
    int m_base = wid * 16;

    // ---- phase A loads: W1 split -> A1, cat split -> B1, misc ----
    const float* w1g = l1w + (size_t)blk * HH * K1;
    for (int idx = tid; idx < HH * K1; idx += 256) {
        int m = idx / K1, k = idx - m * K1;
        __nv_bfloat16 h, l; bsplit(w1g[idx], h, l);
        u32 o = (u32)m * SAB1 + (u32)k * 2u;
        *(__nv_bfloat16*)(sm + O_A1H + o) = h;
        *(__nv_bfloat16*)(sm + O_A1L + o) = l;
    }
    for (int idx = tid; idx < HH * 6; idx += 256) {     // zero-pad k in [154,160)
        int m = idx & 127, k = K1 + (idx >> 7);
        u32 o = (u32)m * SAB1 + (u32)k * 2u;
        *(__nv_bfloat16*)(sm + O_A1H + o) = __float2bfloat16(0.f);
        *(__nv_bfloat16*)(sm + O_A1L + o) = __float2bfloat16(0.f);
    }
    const float* xbase = g_xl + (size_t)b * HH * NN + p0;
    for (int idx = tid; idx < HH * NP; idx += 256) {    // xl features k<128
        int k = idx >> 7, n = idx & 127;
        __nv_bfloat16 h, l; bsplit(xbase[(size_t)k * NN + n], h, l);
        u32 o = (u32)n * SAB1 + (u32)k * 2u;
        *(__nv_bfloat16*)(sm + O_B1H + o) = h;
        *(__nv_bfloat16*)(sm + O_B1L + o) = l;
    }
    for (int idx = tid; idx < (GG + DCC + 6) * NP; idx += 256) {  // xg, ctx, pad
        int r = idx >> 7, n = idx & 127;
        float v = 0.f;
        if (r < GG) v = g_xg[b * GG + r];
        else if (r < GG + DCC) v = ctx[b * DCC + (r - GG)];
        __nv_bfloat16 h, l; bsplit(v, h, l);
        u32 o = (u32)n * SAB1 + (u32)(HH + r) * 2u;
        *(__nv_bfloat16*)(sm + O_B1H + o) = h;
        *(__nv_bfloat16*)(sm + O_B1L + o) = l;
    }
    if (tid < HH) {
        *(float*)(sm + O_B1V + tid * 4) = l1b[blk * HH + tid];
        *(float*)(sm + O_B2V + tid * 4) = l2b[blk * HH + tid];
        *(float*)(sm + O_MK + tid * 4) = mask[(size_t)b * NN + p0 + tid];
    }
    if (last) {
        for (int idx = tid; idx < 3 * HH; idx += 256) *(float*)(sm + O_OW + idx * 4) = outw[idx];
        if (tid < 3) *(float*)(sm + O_OB + tid * 4) = outb[tid];
    }
    __syncthreads();

    // ---- stage 1 GEMM: D1[m, n] over K=160 ----
    float acc[64];
    #pragma unroll
    for (int i = 0; i < 64; ++i) acc[i] = 0.f;
    gemm_ss<10, SAB1, SAB1>(sb + O_A1H, sb + O_A1L, sb + O_B1H, sb + O_B1L,
                            lane, m_base, acc);
    __syncthreads();   // all warps done reading A1/B1

    // ---- epilogue 1: h = lrelu(D1 + b1) -> split into B2; load W2 -> A2 ----
    {
        int r = m_base + (lane >> 2);
        float b1r  = *(const float*)(sm + O_B1V + r * 4);
        float b1r8 = *(const float*)(sm + O_B1V + (r + 8) * 4);
        #pragma unroll
        for (int nt = 0; nt < 16; ++nt) {
            int n0 = nt * 8 + 2 * (lane & 3);
            float v00 = lrelu(acc[nt * 4 + 0] + b1r);
            float v01 = lrelu(acc[nt * 4 + 1] + b1r);
            float v10 = lrelu(acc[nt * 4 + 2] + b1r8);
            float v11 = lrelu(acc[nt * 4 + 3] + b1r8);
            __nv_bfloat16 h, l;
            u32 o00 = (u32)n0 * SAB2 + (u32)r * 2u;
            u32 o01 = (u32)(n0 + 1) * SAB2 + (u32)r * 2u;
            bsplit(v00, h, l);
            *(__nv_bfloat16*)(sm + O_B2H + o00) = h; *(__nv_bfloat16*)(sm + O_B2L + o00) = l;
            bsplit(v01, h, l);
            *(__nv_bfloat16*)(sm + O_B2H + o01) = h; *(__nv_bfloat16*)(sm + O_B2L + o01) = l;
            u32 o10 = o00 + 16u, o11 = o01 + 16u;  // (r+8)*2 = r*2 + 16
            bsplit(v10, h, l);
            *(__nv_bfloat16*)(sm + O_B2H + o10) = h; *(__nv_bfloat16*)(sm + O_B2L + o10) = l;
            bsplit(v11, h, l);
            *(__nv_bfloat16*)(sm + O_B2H + o11) = h; *(__nv_bfloat16*)(sm + O_B2L + o11) = l;
        }
    }
    {
        const float* w2g = l2w + (size_t)blk * HH * HH;
        for (int idx = tid; idx < HH * HH; idx += 256) {
            int m = idx >> 7, k = idx & 127;
            __nv_bfloat16 h, l; bsplit(w2g[idx], h, l);
            u32 o = (u32)m * SAB2 + (u32)k * 2u;
            *(__nv_bfloat16*)(sm + O_A2H + o) = h;
            *(__nv_bfloat16*)(sm + O_A2L + o) = l;
        }
    }
    __syncthreads();

    // ---- stage 2 GEMM: D2[m, n] over K=128 ----
    #pragma unroll
    for (int i = 0; i < 64; ++i) acc[i] = 0.f;
    gemm_ss<8, SAB2, SAB2>(sb + O_A2H, sb + O_A2L, sb + O_B2H, sb + O_B2L,
                           lane, m_base, acc);

    // ---- epilogue 2: xl_new = lrelu(D2 + b2 + xl) * mask ----
    int r = m_base + (lane >> 2);
    float b2r  = *(const float*)(sm + O_B2V + r * 4);
    float b2r8 = *(const float*)(sm + O_B2V + (r + 8) * 4);
    float vout[64];
    float sumA = 0.f, sumB = 0.f;
    #pragma unroll
    for (int nt = 0; nt < 16; ++nt) {
        int n0 = nt * 8 + 2 * (lane & 3);
        float mk0 = *(const float*)(sm + O_MK + n0 * 4);
        float mk1 = *(const float*)(sm + O_MK + (n0 + 1) * 4);
        const float* gr  = g_xl + ((size_t)(b * HH + r)) * NN + p0 + n0;
        const float* gr8 = g_xl + ((size_t)(b * HH + r + 8)) * NN + p0 + n0;
        float2 ra = *(const float2*)gr;
        float2 rb = *(const float2*)gr8;
        float v0 = lrelu(acc[nt * 4 + 0] + b2r + ra.x) * mk0;
        float v1 = lrelu(acc[nt * 4 + 1] + b2r + ra.y) * mk1;
        float v2 = lrelu(acc[nt * 4 + 2] + b2r8 + rb.x) * mk0;
        float v3 = lrelu(acc[nt * 4 + 3] + b2r8 + rb.y) * mk1;
        vout[nt * 4 + 0] = v0; vout[nt * 4 + 1] = v1;
        vout[nt * 4 + 2] = v2; vout[nt * 4 + 3] = v3;
        sumA += v0 + v1; sumB += v2 + v3;
    }

    if (!last) {
        #pragma unroll
        for (int nt = 0; nt < 16; ++nt) {
            int n0 = nt * 8 + 2 * (lane & 3);
            float* gr  = g_xl + ((size_t)(b * HH + r)) * NN + p0 + n0;
            float* gr8 = g_xl + ((size_t)(b * HH + r + 8)) * NN + p0 + n0;
            *(float2*)gr  = make_float2(vout[nt * 4 + 0], vout[nt * 4 + 1]);
            *(float2*)gr8 = make_float2(vout[nt * 4 + 2], vout[nt * 4 + 3]);
        }
        #pragma unroll
        for (int o = 1; o <= 2; o <<= 1) {
            sumA += __shfl_xor_sync(0xffffffffu, sumA, o);
            sumB += __shfl_xor_sync(0xffffffffu, sumB, o);
        }
        if ((lane & 3) == 0) {
            g_part[(b * NT + tile) * HH + r] = sumA;
            g_part[(b * NT + tile) * HH + r + 8] = sumB;
        }
    } else {
        __syncthreads();   // done reading B2 before staging overwrite
        #pragma unroll
        for (int nt = 0; nt < 16; ++nt) {
            int n0 = nt * 8 + 2 * (lane & 3);
            *(float*)(sm + O_STG + ((u32)n0 * 129 + r) * 4)       = vout[nt * 4 + 0];
            *(float*)(sm + O_STG + ((u32)(n0 + 1) * 129 + r) * 4) = vout[nt * 4 + 1];
            *(float*)(sm + O_STG + ((u32)n0 * 129 + r + 8) * 4)       = vout[nt * 4 + 2];
            *(float*)(sm + O_STG + ((u32)(n0 + 1) * 129 + r + 8) * 4) = vout[nt * 4 + 3];
        }
        __syncthreads();
        if (tid < NP) {
            int p = tid;
            float mk = *(const float*)(sm + O_MK + p * 4);
            float s0 = *(const float*)(sm + O_OB + 0);
            float s1 = *(const float*)(sm + O_OB + 4);
            float s2 = *(const float*)(sm + O_OB + 8);
            const float* row = (const float*)(sm + O_STG) + (u32)p * 129;
            for (int m = 0; m < HH; ++m) {
                float v = row[m];
                s0 = fmaf(v, *(const float*)(sm + O_OW + m * 4), s0);
                s1 = fmaf(v, *(const float*)(sm + O_OW + (HH + m) * 4), s1);
                s2 = fmaf(v, *(const float*)(sm + O_OW + (2 * HH + m) * 4), s2);
            }
            float* o = dout + ((size_t)b * NN + p0 + p) * 3;
            o[0] = mk * s0; o[1] = mk * s1; o[2] = mk * s2;
        }
    }
}

// ---------------------------------------------------------------------------
extern "C" void kernel_launch(void* const* d_in, const int* in_sizes, int n_in,
                              void* d_out, int out_size)
{
    const float* x_local = (const float*)d_in[0];
    const float* context = (const float*)d_in[1];
    const float* mask    = (const float*)d_in[2];
    const float* proj_lw = (const float*)d_in[3];
    const float* proj_lb = (const float*)d_in[4];
    const float* pg0w    = (const float*)d_in[5];
    const float* pg0b    = (const float*)d_in[6];
    const float* pg1w    = (const float*)d_in[7];
    const float* pg1b    = (const float*)d_in[8];
    const float* pg2w    = (const float*)d_in[9];
    const float* pg2b    = (const float*)d_in[10];
    const float* g1w     = (const float*)d_in[11];
    const float* g1b     = (const float*)d_in[12];
    const float* g2w     = (const float*)d_in[13];
    const float* g2b     = (const float*)d_in[14];
    const float* l1w     = (const float*)d_in[15];
    const float* l1b     = (const float*)d_in[16];
    const float* l2w     = (const float*)d_in[17];
    const float* l2b     = (const float*)d_in[18];
    const float* outw    = (const float*)d_in[19];
    const float* outb    = (const float*)d_in[20];
    float* out = (float*)d_out;

    cudaFuncSetAttribute(k_local, cudaFuncAttributeMaxDynamicSharedMemorySize, SMEM_SZ);

    k_proj<<<dim3(16, NT0), 256>>>(x_local, mask, proj_lw, proj_lb);
    for (int blk = 0; blk < NBLK; ++blk) {
        k_global<<<16, 128>>>(blk == 0 ? 0 : 1, blk, context,
                              pg0w, pg0b, pg1w, pg1b, pg2w, pg2b,
                              g1w, g1b, g2w, g2b);
        k_local<<<dim3(NT, 16), 256, SMEM_SZ>>>(
            blk, blk == NBLK - 1 ? 1 : 0,
            l1w, l1b, l2w, l2b, context, mask, outw, outb, out);
    }
}

// round 10
// speedup vs baseline: 1.4588x; 1.1229x over previous
#include <cuda_runtime.h>
#include <cuda_bf16.h>
#include <cstdint>

#define BB 16
#define NN 8192
#define HH 128
#define GG 10
#define DCC 16
#define NBLK 6
#define K1 154          // H + G + DC
#define KPROJ0 272
#define KBLK 282
#define NP 128          // points per local CTA
#define NT 64           // local tiles per batch
#define NPART 128       // pooling partial columns per batch (2 per tile)
#define NT0 32          // proj tiles per batch

// ---- k_local dynamic SMEM byte offsets ----
// phase A: A1 = W1 split (128 x 168 bf16, stride 336B), B1 = cat split (128 x 168)
// phase B (after stage-1 sync): B2 = h split (128 x 136, stride 272B) over A1,
//                               A2 = W2 split (128 x 136) over B1.
// last-block: fp32 staging [128][129] over B2 region.
#define SAB1 336
#define SAB2 272
#define O_A1H 0
#define O_A1L 43008
#define O_B1H 86016
#define O_B1L 129024
#define O_B2H 0
#define O_B2L 43008
#define O_A2H 86016
#define O_A2L 129024
#define O_STG 0
#define O_MB  172032
#define O_B1V (O_MB)
#define O_B2V (O_MB + 512)
#define O_MK  (O_MB + 1024)
#define O_OW  (O_MB + 1536)
#define O_OB  (O_MB + 3072)
#define SMEM_SZ 175232

typedef unsigned int u32;

// persistent scratch (allocation-free rule: __device__ globals)
__device__ float g_xl[(size_t)BB * HH * NN];      // (B, H, N)
__device__ float g_part[BB * NPART * HH];
__device__ float g_part0[BB * NT0 * HH];
__device__ float g_cnt0[BB * NT0];
__device__ float g_cnt[BB];
__device__ float g_xg[BB * GG];

__device__ __forceinline__ float lrelu(float v) { return fmaxf(v, 0.01f * v); }

__device__ __forceinline__ u32 s2u(const void* p) {
    u32 a;
    asm("{ .reg .u64 t; cvta.to.shared.u64 t, %1; cvt.u32.u64 %0, t; }" : "=r"(a) : "l"(p));
    return a;
}
__device__ __forceinline__ void bsplit(float v, __nv_bfloat16& h, __nv_bfloat16& l) {
    h = __float2bfloat16(v);
    l = __float2bfloat16(v - __bfloat162float(h));
}

#define LDM4(r, addr) \
    asm volatile("ldmatrix.sync.aligned.m8n8.x4.shared.b16 {%0,%1,%2,%3}, [%4];" \
        : "=r"((r)[0]), "=r"((r)[1]), "=r"((r)[2]), "=r"((r)[3]) : "r"(addr))

#define MMA(c, a, b0_, b1_) \
    asm volatile("mma.sync.aligned.m16n8k16.row.col.f32.bf16.bf16.f32 " \
        "{%0,%1,%2,%3}, {%4,%5,%6,%7}, {%8,%9}, {%0,%1,%2,%3};" \
        : "+f"((c)[0]), "+f"((c)[1]), "+f"((c)[2]), "+f"((c)[3]) \
        : "r"((a)[0]), "r"((a)[1]), "r"((a)[2]), "r"((a)[3]), "r"(b0_), "r"(b1_))

// D[16 x 64 per warp] += (2-term split) A[m, k] x B[n, k]^T, 3 MMAs per tile.
template<int KST, int SAb, int SBb>
__device__ __forceinline__ void gemm_ss(u32 aH, u32 aL, u32 bH, u32 bL,
                                        int lane, int m_base, int n_base, float* acc)
{
    u32 aOff  = aH + (u32)(m_base + (lane & 15)) * SAb + ((lane & 16) ? 16u : 0u);
    u32 aOffL = aOff + (aL - aH);
    u32 bRow = (u32)((lane & 7) + ((lane & 16) >> 1));
    u32 bOff  = bH + ((u32)n_base + bRow) * SBb + ((lane & 8) ? 16u : 0u);
    u32 bOffL = bOff + (bL - bH);
    #pragma unroll 2
    for (int ks = 0; ks < KST; ++ks) {
        u32 ak = (u32)ks * 32u;
        u32 ah[4], al[4];
        LDM4(ah, aOff + ak);
        LDM4(al, aOffL + ak);
        #pragma unroll
        for (int np = 0; np < 4; ++np) {
            u32 bk = (u32)(np * 16) * SBb + ak;
            u32 bh[4], bl[4];
            LDM4(bh, bOff + bk);
            LDM4(bl, bOffL + bk);
            float* c0 = acc + (2 * np) * 4;
            float* c1 = acc + (2 * np + 1) * 4;
            MMA(c0, ah, bh[0], bh[1]);
            MMA(c0, ah, bl[0], bl[1]);
            MMA(c0, al, bh[0], bh[1]);
            MMA(c1, ah, bh[2], bh[3]);
            MMA(c1, ah, bl[2], bl[3]);
            MMA(c1, al, bh[2], bh[3]);
        }
    }
}

// ---------------------------------------------------------------------------
// k_proj: xl0 = lrelu(x @ proj_lw^T + b) * mask into g_xl (B,H,N),
//         fused pooling partials + mask counts. grid (16, 32), 256 thr.
// ---------------------------------------------------------------------------
__global__ __launch_bounds__(256) void k_proj(
    const float* __restrict__ x, const float* __restrict__ mask,
    const float* __restrict__ lw, const float* __restrict__ lb)
{
    __shared__ float sw[HH * 3], sbv[HH], st[32][257], sp[HH], sc[8];
    int b = blockIdx.x, tile = blockIdx.y, tid = threadIdx.x;
    int wid = tid >> 5, lid = tid & 31;
    int p0 = tile * 256, p = p0 + tid;
    for (int i = tid; i < HH * 3; i += 256) sw[i] = lw[i];
    for (int i = tid; i < HH; i += 256) { sbv[i] = lb[i]; sp[i] = 0.f; }
    __syncthreads();
    const float* xr = x + ((size_t)b * NN + p) * 3;
    float x0 = xr[0], x1 = xr[1], x2 = xr[2];
    float m = mask[(size_t)b * NN + p];
    float cacc = m;
    #pragma unroll
    for (int o = 16; o; o >>= 1) cacc += __shfl_xor_sync(0xffffffffu, cacc, o);
    if (lid == 0) sc[wid] = cacc;

    for (int hc = 0; hc < 4; ++hc) {
        #pragma unroll
        for (int r = 0; r < 32; ++r) {
            int h = hc * 32 + r;
            float v = fmaf(x0, sw[h * 3], fmaf(x1, sw[h * 3 + 1], fmaf(x2, sw[h * 3 + 2], sbv[h])));
            st[r][tid] = lrelu(v) * m;
        }
        __syncthreads();
        for (int idx = tid; idx < 32 * 256; idx += 256) {
            int r = idx >> 8, q = idx & 255;
            g_xl[(size_t)b * HH * NN + (size_t)(hc * 32 + r) * NN + p0 + q] = st[r][q];
        }
        #pragma unroll
        for (int rr = 0; rr < 4; ++rr) {
            int r = wid * 4 + rr;
            float a = 0.f;
            #pragma unroll
            for (int q = 0; q < 8; ++q) a += st[r][lid + q * 32];
            #pragma unroll
            for (int o = 16; o; o >>= 1) a += __shfl_xor_sync(0xffffffffu, a, o);
            if (lid == 0) sp[hc * 32 + r] += a;
        }
        __syncthreads();
    }
    if (tid < HH) g_part0[(b * NT0 + tile) * HH + tid] = sp[tid];
    if (tid == 0) {
        float c = 0.f;
        #pragma unroll
        for (int i = 0; i < 8; ++i) c += sc[i];
        g_cnt0[b * NT0 + tile] = c;
    }
}

// ---------------------------------------------------------------------------
// k_global: warp-per-output dots (coalesced weight reads). grid 16, 128 thr.
// ---------------------------------------------------------------------------
__device__ __forceinline__ float dotw(const float* __restrict__ w,
                                      const float* __restrict__ xs, int n, int lid) {
    float a = 0.f;
    for (int k = lid; k < n; k += 32) a = fmaf(w[k], xs[k], a);
    #pragma unroll
    for (int o = 16; o; o >>= 1) a += __shfl_xor_sync(0xffffffffu, a, o);
    return a;
}

__global__ __launch_bounds__(128) void k_global(
    int phase, int blk, const float* __restrict__ ctx,
    const float* __restrict__ pg0w, const float* __restrict__ pg0b,
    const float* __restrict__ pg1w, const float* __restrict__ pg1b,
    const float* __restrict__ pg2w, const float* __restrict__ pg2b,
    const float* __restrict__ g1w, const float* __restrict__ g1b,
    const float* __restrict__ g2w, const float* __restrict__ g2b)
{
    __shared__ float sp[KBLK], spP[KPROJ0], sh[HH], sh2[HH], sxg[GG];
    __shared__ float scn;
    int b = blockIdx.x, j = threadIdx.x, wid = j >> 5, lid = j & 31;

    float s = 0.f;
    if (phase == 0) {
        #pragma unroll 4
        for (int c = 0; c < NT0; ++c) s += g_part0[(b * NT0 + c) * HH + j];
        if (j == 0) {
            float cc = 0.f;
            for (int c = 0; c < NT0; ++c) cc += g_cnt0[b * NT0 + c];
            scn = cc; g_cnt[b] = cc;
        }
    } else {
        #pragma unroll 4
        for (int c = 0; c < NPART; ++c) s += g_part[(b * NPART + c) * HH + j];
        if (j == 0) scn = g_cnt[b];
    }
    __syncthreads();
    float cnt = scn;
    sp[j] = s / cnt; sp[HH + j] = s;
    if (phase == 0) {
        spP[j] = s / cnt; spP[HH + j] = s;
        if (j < DCC) spP[2 * HH + j] = ctx[b * DCC + j];
    }
    if (j < DCC) sp[2 * HH + GG + j] = ctx[b * DCC + j];
    __syncthreads();

    if (phase == 0) {
        for (int o = wid; o < HH; o += 4) {
            float a = dotw(pg0w + (size_t)o * KPROJ0, spP, KPROJ0, lid);
            if (lid == 0) sh[o] = lrelu(a + pg0b[o]);
        }
        __syncthreads();
        for (int o = wid; o < HH; o += 4) {
            float a = dotw(pg1w + (size_t)o * HH, sh, HH, lid);
            if (lid == 0) sh2[o] = lrelu(a + pg1b[o]);
        }
        __syncthreads();
        for (int o = wid; o < GG; o += 4) {
            float a = dotw(pg2w + (size_t)o * HH, sh2, HH, lid);
            if (lid == 0) sxg[o] = lrelu(a + pg2b[o]);
        }
        __syncthreads();
    } else {
        if (j < GG) sxg[j] = g_xg[b * GG + j];
        __syncthreads();
    }

    if (j < GG) sp[2 * HH + j] = sxg[j];
    __syncthreads();
    for (int o = wid; o < HH; o += 4) {
        float a = dotw(g1w + ((size_t)blk * HH + o) * KBLK, sp, KBLK, lid);
        if (lid == 0) sh[o] = lrelu(a + g1b[blk * HH + o]);
    }
    __syncthreads();
    for (int o = wid; o < GG; o += 4) {
        float a = dotw(g2w + ((size_t)blk * GG + o) * HH, sh, HH, lid) + g2b[blk * GG + o];
        if (lid == 0) g_xg[b * GG + o] = lrelu(a + sxg[o]);
    }
}

// ---------------------------------------------------------------------------
// k_local: mma.sync bf16-split two-layer MLP + residual + pooling partials.
// grid (64 tiles, 16 b), 512 threads = 16 warps: warp (mw, nh) owns
// M rows [mw*16, +16) x N points [nh*64, +64). acc = 32 regs, no spills.
// ---------------------------------------------------------------------------
extern __shared__ char smem[];

__global__ void __launch_bounds__(512, 1) k_local(
    int blk, int last,
    const float* __restrict__ l1w, const float* __restrict__ l1b,
    const float* __restrict__ l2w, const float* __restrict__ l2b,
    const float* __restrict__ ctx, const float* __restrict__ mask,
    const float* __restrict__ outw, const float* __restrict__ outb,
    float* __restrict__ dout)
{
    char* sm = smem;
    u32 sb = s2u(sm);
    int tile = blockIdx.x, b = blockIdx.y, tid = threadIdx.x;
    int wid = tid >> 5, lane = tid & 31;
    int p0 = tile * NP;
    int mw = wid & 7, nh = wid >> 3;
    int m_base = mw * 16, n_base = nh * 64;

    // ---- phase A loads: W1 split -> A1, cat split -> B1, misc ----
    const float* w1g = l1w + (size_t)blk * HH * K1;
    for (int idx = tid; idx < HH * K1; idx += 512) {
        int m = idx / K1, k = idx - m * K1;
        __nv_bfloat16 h, l; bsplit(w1g[idx], h, l);
        u32 o = (u32)m * SAB1 + (u32)k * 2u;
        *(__nv_bfloat16*)(sm + O_A1H + o) = h;
        *(__nv_bfloat16*)(sm + O_A1L + o) = l;
    }
    for (int idx = tid; idx < HH * 6; idx += 512) {     // zero-pad k in [154,160)
        int m = idx & 127, k = K1 + (idx >> 7);
        u32 o = (u32)m * SAB1 + (u32)k * 2u;
        *(__nv_bfloat16*)(sm + O_A1H + o) = __float2bfloat16(0.f);
        *(__nv_bfloat16*)(sm + O_A1L + o) = __float2bfloat16(0.f);
    }
    const float* xbase = g_xl + (size_t)b * HH * NN + p0;
    for (int idx = tid; idx < HH * NP; idx += 512) {    // xl features k<128
        int k = idx >> 7, n = idx & 127;
        __nv_bfloat16 h, l; bsplit(xbase[(size_t)k * NN + n], h, l);
        u32 o = (u32)n * SAB1 + (u32)k * 2u;
        *(__nv_bfloat16*)(sm + O_B1H + o) = h;
        *(__nv_bfloat16*)(sm + O_B1L + o) = l;
    }
    for (int idx = tid; idx < (GG + DCC + 6) * NP; idx += 512) {  // xg, ctx, pad
        int r = idx >> 7, n = idx & 127;
        float v = 0.f;
        if (r < GG) v = g_xg[b * GG + r];
        else if (r < GG + DCC) v = ctx[b * DCC + (r - GG)];
        __nv_bfloat16 h, l; bsplit(v, h, l);
        u32 o = (u32)n * SAB1 + (u32)(HH + r) * 2u;
        *(__nv_bfloat16*)(sm + O_B1H + o) = h;
        *(__nv_bfloat16*)(sm + O_B1L + o) = l;
    }
    if (tid < HH) {
        *(float*)(sm + O_B1V + tid * 4) = l1b[blk * HH + tid];
        *(float*)(sm + O_B2V + tid * 4) = l2b[blk * HH + tid];
        *(float*)(sm + O_MK + tid * 4) = mask[(size_t)b * NN + p0 + tid];
    }
    if (last) {
        for (int idx = tid; idx < 3 * HH; idx += 512) *(float*)(sm + O_OW + idx * 4) = outw[idx];
        if (tid < 3) *(float*)(sm + O_OB + tid * 4) = outb[tid];
    }
    __syncthreads();

    // ---- stage 1 GEMM: D1[m, n] over K=160 ----
    float acc[32];
    #pragma unroll
    for (int i = 0; i < 32; ++i) acc[i] = 0.f;
    gemm_ss<10, SAB1, SAB1>(sb + O_A1H, sb + O_A1L, sb + O_B1H, sb + O_B1L,
                            lane, m_base, n_base, acc);
    __syncthreads();   // all warps done reading A1/B1

    // ---- epilogue 1: h = lrelu(D1 + b1) -> split into B2; load W2 -> A2 ----
    int r = m_base + (lane >> 2);
    {
        float b1r  = *(const float*)(sm + O_B1V + r * 4);
        float b1r8 = *(const float*)(sm + O_B1V + (r + 8) * 4);
        #pragma unroll
        for (int nt = 0; nt < 8; ++nt) {
            int n0 = n_base + nt * 8 + 2 * (lane & 3);
            float v00 = lrelu(acc[nt * 4 + 0] + b1r);
            float v01 = lrelu(acc[nt * 4 + 1] + b1r);
            float v10 = lrelu(acc[nt * 4 + 2] + b1r8);
            float v11 = lrelu(acc[nt * 4 + 3] + b1r8);
            __nv_bfloat16 h, l;
            u32 o00 = (u32)n0 * SAB2 + (u32)r * 2u;
            u32 o01 = (u32)(n0 + 1) * SAB2 + (u32)r * 2u;
            bsplit(v00, h, l);
            *(__nv_bfloat16*)(sm + O_B2H + o00) = h; *(__nv_bfloat16*)(sm + O_B2L + o00) = l;
            bsplit(v01, h, l);
            *(__nv_bfloat16*)(sm + O_B2H + o01) = h; *(__nv_bfloat16*)(sm + O_B2L + o01) = l;
            u32 o10 = o00 + 16u, o11 = o01 + 16u;  // (r+8)*2 = r*2 + 16
            bsplit(v10, h, l);
            *(__nv_bfloat16*)(sm + O_B2H + o10) = h; *(__nv_bfloat16*)(sm + O_B2L + o10) = l;
            bsplit(v11, h, l);
            *(__nv_bfloat16*)(sm + O_B2H + o11) = h; *(__nv_bfloat16*)(sm + O_B2L + o11) = l;
        }
    }
    {
        const float* w2g = l2w + (size_t)blk * HH * HH;
        for (int idx = tid; idx < HH * HH; idx += 512) {
            int m = idx >> 7, k = idx & 127;
            __nv_bfloat16 h, l; bsplit(w2g[idx], h, l);
            u32 o = (u32)m * SAB2 + (u32)k * 2u;
            *(__nv_bfloat16*)(sm + O_A2H + o) = h;
            *(__nv_bfloat16*)(sm + O_A2L + o) = l;
        }
    }
    __syncthreads();

    // ---- stage 2 GEMM: D2[m, n] over K=128 ----
    #pragma unroll
    for (int i = 0; i < 32; ++i) acc[i] = 0.f;
    gemm_ss<8, SAB2, SAB2>(sb + O_A2H, sb + O_A2L, sb + O_B2H, sb + O_B2L,
                           lane, m_base, n_base, acc);

    // ---- epilogue 2: xl_new = lrelu(D2 + b2 + xl) * mask, streamed out ----
    float b2r  = *(const float*)(sm + O_B2V + r * 4);
    float b2r8 = *(const float*)(sm + O_B2V + (r + 8) * 4);
    float sumA = 0.f, sumB = 0.f;

    if (!last) {
        #pragma unroll
        for (int nt = 0; nt < 8; ++nt) {
            int n0 = n_base + nt * 8 + 2 * (lane & 3);
            float mk0 = *(const float*)(sm + O_MK + n0 * 4);
            float mk1 = *(const float*)(sm + O_MK + (n0 + 1) * 4);
            float* gr  = g_xl + ((size_t)(b * HH + r)) * NN + p0 + n0;
            float* gr8 = g_xl + ((size_t)(b * HH + r + 8)) * NN + p0 + n0;
            float2 ra = *(const float2*)gr;
            float2 rb = *(const float2*)gr8;
            float v0 = lrelu(acc[nt * 4 + 0] + b2r + ra.x) * mk0;
            float v1 = lrelu(acc[nt * 4 + 1] + b2r + ra.y) * mk1;
            float v2 = lrelu(acc[nt * 4 + 2] + b2r8 + rb.x) * mk0;
            float v3 = lrelu(acc[nt * 4 + 3] + b2r8 + rb.y) * mk1;
            *(float2*)gr  = make_float2(v0, v1);
            *(float2*)gr8 = make_float2(v2, v3);
            sumA += v0 + v1; sumB += v2 + v3;
        }
        #pragma unroll
        for (int o = 1; o <= 2; o <<= 1) {
            sumA += __shfl_xor_sync(0xffffffffu, sumA, o);
            sumB += __shfl_xor_sync(0xffffffffu, sumB, o);
        }
        if ((lane & 3) == 0) {
            int pc = b * NPART + tile * 2 + nh;
            g_part[pc * HH + r] = sumA;
            g_part[pc * HH + r + 8] = sumB;
        }
    } else {
        __syncthreads();   // done reading B2/A2 before staging overwrite
        #pragma unroll
        for (int nt = 0; nt < 8; ++nt) {
            int n0 = n_base + nt * 8 + 2 * (lane & 3);
            float mk0 = *(const float*)(sm + O_MK + n0 * 4);
            float mk1 = *(const float*)(sm + O_MK + (n0 + 1) * 4);
            const float* gr  = g_xl + ((size_t)(b * HH + r)) * NN + p0 + n0;
            const float* gr8 = g_xl + ((size_t)(b * HH + r + 8)) * NN + p0 + n0;
            float2 ra = *(const float2*)gr;
            float2 rb = *(const float2*)gr8;
            float v0 = lrelu(acc[nt * 4 + 0] + b2r + ra.x) * mk0;
            float v1 = lrelu(acc[nt * 4 + 1] + b2r + ra.y) * mk1;
            float v2 = lrelu(acc[nt * 4 + 2] + b2r8 + rb.x) * mk0;
            float v3 = lrelu(acc[nt * 4 + 3] + b2r8 + rb.y) * mk1;
            *(float*)(sm + O_STG + ((u32)n0 * 129 + r) * 4)           = v0;
            *(float*)(sm + O_STG + ((u32)(n0 + 1) * 129 + r) * 4)     = v1;
            *(float*)(sm + O_STG + ((u32)n0 * 129 + r + 8) * 4)       = v2;
            *(float*)(sm + O_STG + ((u32)(n0 + 1) * 129 + r + 8) * 4) = v3;
        }
        __syncthreads();
        if (tid < NP) {
            int p = tid;
            float mk = *(const float*)(sm + O_MK + p * 4);
            float s0 = *(const float*)(sm + O_OB + 0);
            float s1 = *(const float*)(sm + O_OB + 4);
            float s2 = *(const float*)(sm + O_OB + 8);
            const float* row = (const float*)(sm + O_STG) + (u32)p * 129;
            for (int m = 0; m < HH; ++m) {
                float v = row[m];
                s0 = fmaf(v, *(const float*)(sm + O_OW + m * 4), s0);
                s1 = fmaf(v, *(const float*)(sm + O_OW + (HH + m) * 4), s1);
                s2 = fmaf(v, *(const float*)(sm + O_OW + (2 * HH + m) * 4), s2);
            }
            float* o = dout + ((size_t)b * NN + p0 + p) * 3;
            o[0] = mk * s0; o[1] = mk * s1; o[2] = mk * s2;
        }
    }
}

// ---------------------------------------------------------------------------
extern "C" void kernel_launch(void* const* d_in, const int* in_sizes, int n_in,
                              void* d_out, int out_size)
{
    const float* x_local = (const float*)d_in[0];
    const float* context = (const float*)d_in[1];
    const float* mask    = (const float*)d_in[2];
    const float* proj_lw = (const float*)d_in[3];
    const float* proj_lb = (const float*)d_in[4];
    const float* pg0w    = (const float*)d_in[5];
    const float* pg0b    = (const float*)d_in[6];
    const float* pg1w    = (const float*)d_in[7];
    const float* pg1b    = (const float*)d_in[8];
    const float* pg2w    = (const float*)d_in[9];
    const float* pg2b    = (const float*)d_in[10];
    const float* g1w     = (const float*)d_in[11];
    const float* g1b     = (const float*)d_in[12];
    const float* g2w     = (const float*)d_in[13];
    const float* g2b     = (const float*)d_in[14];
    const float* l1w     = (const float*)d_in[15];
    const float* l1b     = (const float*)d_in[16];
    const float* l2w     = (const float*)d_in[17];
    const float* l2b     = (const float*)d_in[18];
    const float* outw    = (const float*)d_in[19];
    const float* outb    = (const float*)d_in[20];
    float* out = (float*)d_out;

    cudaFuncSetAttribute(k_local, cudaFuncAttributeMaxDynamicSharedMemorySize, SMEM_SZ);

    k_proj<<<dim3(16, NT0), 256>>>(x_local, mask, proj_lw, proj_lb);
    for (int blk = 0; blk < NBLK; ++blk) {
        k_global<<<16, 128>>>(blk == 0 ? 0 : 1, blk, context,
                              pg0w, pg0b, pg1w, pg1b, pg2w, pg2b,
                              g1w, g1b, g2w, g2b);
        k_local<<<dim3(NT, 16), 512, SMEM_SZ>>>(
            blk, blk == NBLK - 1 ? 1 : 0,
            l1w, l1b, l2w, l2b, context, mask, outw, outb, out);
    }
}

// round 11
// speedup vs baseline: 1.6202x; 1.1106x over previous
#include <cuda_runtime.h>
#include <cuda_bf16.h>
#include <cstdint>

#define BB 16
#define NN 8192
#define HH 128
#define GG 10
#define DCC 16
#define NBLK 6
#define K1 154          // H + G + DC (global-path cat width only now)
#define KPROJ0 272
#define KBLK 282
#define NP 128          // points per local CTA
#define NT 64           // local tiles per batch
#define NPART 128       // pooling partial columns per batch (2 per tile)
#define NT0 32          // proj tiles per batch

// ---- k_local SMEM: six 128x128 bf16 tiles, stride 272B (17x16B, conflict-free)
#define SAB 272
#define TILE_B (HH * SAB)       // 34816
#define O_A1H 0
#define O_A1L (TILE_B)
#define O_B1H (2 * TILE_B)
#define O_B1L (3 * TILE_B)
#define O_A2H (4 * TILE_B)
#define O_A2L (5 * TILE_B)
#define O_B2H 0                 // h split overlays A1 after stage-1 sync
#define O_B2L (TILE_B)
#define O_STG 0                 // fp32 staging [128][129] (last block, after GEMM2)
#define O_MB  (6 * TILE_B)      // 208896
#define O_B1V (O_MB)            // l1b + folded xg/ctx term (fp32[128])
#define O_B2V (O_MB + 512)
#define O_MK  (O_MB + 1024)
#define O_OW  (O_MB + 1536)
#define O_OB  (O_MB + 3072)
#define SMEM_SZ (O_MB + 3104)   // 212000 bytes

typedef unsigned int u32;

// persistent scratch (allocation-free rule: __device__ globals)
__device__ float g_xl[(size_t)BB * HH * NN];      // (B, H, N)
__device__ float g_part[BB * NPART * HH];
__device__ float g_part0[BB * NT0 * HH];
__device__ float g_cnt0[BB * NT0];
__device__ float g_cnt[BB];
__device__ float g_xg[BB * GG];
__device__ float g_hb[BB * HH];                   // folded W1[:,128:154]@[xg;ctx]

__device__ __forceinline__ float lrelu(float v) { return fmaxf(v, 0.01f * v); }

__device__ __forceinline__ u32 s2u(const void* p) {
    u32 a;
    asm("{ .reg .u64 t; cvta.to.shared.u64 t, %1; cvt.u32.u64 %0, t; }" : "=r"(a) : "l"(p));
    return a;
}
__device__ __forceinline__ void bsplit(float v, __nv_bfloat16& h, __nv_bfloat16& l) {
    h = __float2bfloat16(v);
    l = __float2bfloat16(v - __bfloat162float(h));
}

#define LDM4(r, addr) \
    asm volatile("ldmatrix.sync.aligned.m8n8.x4.shared.b16 {%0,%1,%2,%3}, [%4];" \
        : "=r"((r)[0]), "=r"((r)[1]), "=r"((r)[2]), "=r"((r)[3]) : "r"(addr))

#define MMA(c, a, b0_, b1_) \
    asm volatile("mma.sync.aligned.m16n8k16.row.col.f32.bf16.bf16.f32 " \
        "{%0,%1,%2,%3}, {%4,%5,%6,%7}, {%8,%9}, {%0,%1,%2,%3};" \
        : "+f"((c)[0]), "+f"((c)[1]), "+f"((c)[2]), "+f"((c)[3]) \
        : "r"((a)[0]), "r"((a)[1]), "r"((a)[2]), "r"((a)[3]), "r"(b0_), "r"(b1_))

// D[16 x 64 per warp] += (2-term split) A[m,k] x B[n,k]^T over K=128.
// All 8 B fragments preloaded per k-step; 24 MMAs round-robin over the 8
// accumulator quads (same-acc reuse distance = 8) to break RAW chains.
__device__ __forceinline__ void gemm_ss(u32 aH, u32 aL, u32 bH, u32 bL,
                                        int lane, int m_base, int n_base, float* acc)
{
    u32 aOff  = aH + (u32)(m_base + (lane & 15)) * SAB + ((lane & 16) ? 16u : 0u);
    u32 aOffL = aOff + (aL - aH);
    u32 bRow = (u32)((lane & 7) + ((lane & 16) >> 1));
    u32 bOff  = bH + ((u32)n_base + bRow) * SAB + ((lane & 8) ? 16u : 0u);
    u32 bOffL = bOff + (bL - bH);
    #pragma unroll 2
    for (int ks = 0; ks < 8; ++ks) {
        u32 ak = (u32)ks * 32u;
        u32 ah[4], al[4];
        LDM4(ah, aOff + ak);
        LDM4(al, aOffL + ak);
        u32 bh[4][4], bl[4][4];
        #pragma unroll
        for (int np = 0; np < 4; ++np) {
            u32 bk = (u32)(np * 16) * SAB + ak;
            LDM4(bh[np], bOff + bk);
            LDM4(bl[np], bOffL + bk);
        }
        #pragma unroll
        for (int np = 0; np < 4; ++np) {
            MMA(acc + 8 * np,     ah, bh[np][0], bh[np][1]);
            MMA(acc + 8 * np + 4, ah, bh[np][2], bh[np][3]);
        }
        #pragma unroll
        for (int np = 0; np < 4; ++np) {
            MMA(acc + 8 * np,     ah, bl[np][0], bl[np][1]);
            MMA(acc + 8 * np + 4, ah, bl[np][2], bl[np][3]);
        }
        #pragma unroll
        for (int np = 0; np < 4; ++np) {
            MMA(acc + 8 * np,     al, bh[np][0], bh[np][1]);
            MMA(acc + 8 * np + 4, al, bh[np][2], bh[np][3]);
        }
    }
}

// ---------------------------------------------------------------------------
// k_proj: xl0 = lrelu(x @ proj_lw^T + b) * mask into g_xl (B,H,N),
//         fused pooling partials + mask counts. grid (16, 32), 256 thr.
// ---------------------------------------------------------------------------
__global__ __launch_bounds__(256) void k_proj(
    const float* __restrict__ x, const float* __restrict__ mask,
    const float* __restrict__ lw, const float* __restrict__ lb)
{
    __shared__ float sw[HH * 3], sbv[HH], st[32][257], sp[HH], sc[8];
    int b = blockIdx.x, tile = blockIdx.y, tid = threadIdx.x;
    int wid = tid >> 5, lid = tid & 31;
    int p0 = tile * 256, p = p0 + tid;
    for (int i = tid; i < HH * 3; i += 256) sw[i] = lw[i];
    for (int i = tid; i < HH; i += 256) { sbv[i] = lb[i]; sp[i] = 0.f; }
    __syncthreads();
    const float* xr = x + ((size_t)b * NN + p) * 3;
    float x0 = xr[0], x1 = xr[1], x2 = xr[2];
    float m = mask[(size_t)b * NN + p];
    float cacc = m;
    #pragma unroll
    for (int o = 16; o; o >>= 1) cacc += __shfl_xor_sync(0xffffffffu, cacc, o);
    if (lid == 0) sc[wid] = cacc;

    for (int hc = 0; hc < 4; ++hc) {
        #pragma unroll
        for (int r = 0; r < 32; ++r) {
            int h = hc * 32 + r;
            float v = fmaf(x0, sw[h * 3], fmaf(x1, sw[h * 3 + 1], fmaf(x2, sw[h * 3 + 2], sbv[h])));
            st[r][tid] = lrelu(v) * m;
        }
        __syncthreads();
        for (int idx = tid; idx < 32 * 256; idx += 256) {
            int r = idx >> 8, q = idx & 255;
            g_xl[(size_t)b * HH * NN + (size_t)(hc * 32 + r) * NN + p0 + q] = st[r][q];
        }
        #pragma unroll
        for (int rr = 0; rr < 4; ++rr) {
            int r = wid * 4 + rr;
            float a = 0.f;
            #pragma unroll
            for (int q = 0; q < 8; ++q) a += st[r][lid + q * 32];
            #pragma unroll
            for (int o = 16; o; o >>= 1) a += __shfl_xor_sync(0xffffffffu, a, o);
            if (lid == 0) sp[hc * 32 + r] += a;
        }
        __syncthreads();
    }
    if (tid < HH) g_part0[(b * NT0 + tile) * HH + tid] = sp[tid];
    if (tid == 0) {
        float c = 0.f;
        #pragma unroll
        for (int i = 0; i < 8; ++i) c += sc[i];
        g_cnt0[b * NT0 + tile] = c;
    }
}

// ---------------------------------------------------------------------------
// k_global: global MLP path + folded-bias vector for k_local. grid 16, 128 thr.
// ---------------------------------------------------------------------------
__device__ __forceinline__ float dotw(const float* __restrict__ w,
                                      const float* __restrict__ xs, int n, int lid) {
    float a = 0.f;
    for (int k = lid; k < n; k += 32) a = fmaf(w[k], xs[k], a);
    #pragma unroll
    for (int o = 16; o; o >>= 1) a += __shfl_xor_sync(0xffffffffu, a, o);
    return a;
}

__global__ __launch_bounds__(128) void k_global(
    int phase, int blk, const float* __restrict__ ctx,
    const float* __restrict__ pg0w, const float* __restrict__ pg0b,
    const float* __restrict__ pg1w, const float* __restrict__ pg1b,
    const float* __restrict__ pg2w, const float* __restrict__ pg2b,
    const float* __restrict__ g1w, const float* __restrict__ g1b,
    const float* __restrict__ g2w, const float* __restrict__ g2b,
    const float* __restrict__ l1w)
{
    __shared__ float sp[KBLK], spP[KPROJ0], sh[HH], sh2[HH], sxg[GG], sgc[GG + DCC];
    __shared__ float scn;
    int b = blockIdx.x, j = threadIdx.x, wid = j >> 5, lid = j & 31;

    float s = 0.f;
    if (phase == 0) {
        #pragma unroll 8
        for (int c = 0; c < NT0; ++c) s += g_part0[(b * NT0 + c) * HH + j];
        if (j == 0) {
            float cc = 0.f;
            for (int c = 0; c < NT0; ++c) cc += g_cnt0[b * NT0 + c];
            scn = cc; g_cnt[b] = cc;
        }
    } else {
        #pragma unroll 8
        for (int c = 0; c < NPART; ++c) s += g_part[(b * NPART + c) * HH + j];
        if (j == 0) scn = g_cnt[b];
    }
    __syncthreads();
    float cnt = scn;
    sp[j] = s / cnt; sp[HH + j] = s;
    if (phase == 0) {
        spP[j] = s / cnt; spP[HH + j] = s;
        if (j < DCC) spP[2 * HH + j] = ctx[b * DCC + j];
    }
    if (j < DCC) sp[2 * HH + GG + j] = ctx[b * DCC + j];
    if (j < DCC) sgc[GG + j] = ctx[b * DCC + j];
    __syncthreads();

    if (phase == 0) {
        for (int o = wid; o < HH; o += 4) {
            float a = dotw(pg0w + (size_t)o * KPROJ0, spP, KPROJ0, lid);
            if (lid == 0) sh[o] = lrelu(a + pg0b[o]);
        }
        __syncthreads();
        for (int o = wid; o < HH; o += 4) {
            float a = dotw(pg1w + (size_t)o * HH, sh, HH, lid);
            if (lid == 0) sh2[o] = lrelu(a + pg1b[o]);
        }
        __syncthreads();
        for (int o = wid; o < GG; o += 4) {
            float a = dotw(pg2w + (size_t)o * HH, sh2, HH, lid);
            if (lid == 0) sxg[o] = lrelu(a + pg2b[o]);
        }
        __syncthreads();
    } else {
        if (j < GG) sxg[j] = g_xg[b * GG + j];
        __syncthreads();
    }

    if (j < GG) sp[2 * HH + j] = sxg[j];
    __syncthreads();
    for (int o = wid; o < HH; o += 4) {
        float a = dotw(g1w + ((size_t)blk * HH + o) * KBLK, sp, KBLK, lid);
        if (lid == 0) sh[o] = lrelu(a + g1b[blk * HH + o]);
    }
    __syncthreads();
    for (int o = wid; o < GG; o += 4) {
        float a = dotw(g2w + ((size_t)blk * GG + o) * HH, sh, HH, lid) + g2b[blk * GG + o];
        if (lid == 0) {
            float v = lrelu(a + sxg[o]);
            g_xg[b * GG + o] = v;
            sgc[o] = v;            // NEW xg for the folded bias
        }
    }
    __syncthreads();

    // folded bias: hb[m] = W1[m, 128:154] @ [xg_new; ctx]
    for (int o = wid; o < HH; o += 4) {
        const float* wrow = l1w + ((size_t)blk * HH + o) * K1 + HH;
        float a = 0.f;
        if (lid < GG + DCC) a = wrow[lid] * sgc[lid];
        #pragma unroll
        for (int of = 16; of; of >>= 1) a += __shfl_xor_sync(0xffffffffu, a, of);
        if (lid == 0) g_hb[b * HH + o] = a;
    }
}

// ---------------------------------------------------------------------------
// k_local: mma.sync bf16-split two-layer MLP, K=128 both stages (xg/ctx folded
// into bias). grid (64 tiles, 16 b), 512 thr = 16 warps (8 M x 2 N-halves).
// ---------------------------------------------------------------------------
extern __shared__ char smem[];

__global__ void __launch_bounds__(512, 1) k_local(
    int blk, int last,
    const float* __restrict__ l1w, const float* __restrict__ l1b,
    const float* __restrict__ l2w, const float* __restrict__ l2b,
    const float* __restrict__ mask,
    const float* __restrict__ outw, const float* __restrict__ outb,
    float* __restrict__ dout)
{
    char* sm = smem;
    u32 sb = s2u(sm);
    int tile = blockIdx.x, b = blockIdx.y, tid = threadIdx.x;
    int wid = tid >> 5, lane = tid & 31;
    int p0 = tile * NP;
    int mw = wid & 7, nh = wid >> 3;
    int m_base = mw * 16, n_base = nh * 64;

    // ---- prologue: W1[:, :128] -> A1, W2 -> A2, xl -> B1, misc ----
    const float* w1g = l1w + (size_t)blk * HH * K1;
    for (int idx = tid; idx < HH * HH; idx += 512) {
        int m = idx >> 7, k = idx & 127;
        __nv_bfloat16 h, l; bsplit(w1g[(size_t)m * K1 + k], h, l);
        u32 o = (u32)m * SAB + (u32)k * 2u;
        *(__nv_bfloat16*)(sm + O_A1H + o) = h;
        *(__nv_bfloat16*)(sm + O_A1L + o) = l;
    }
    const float* w2g = l2w + (size_t)blk * HH * HH;
    for (int idx = tid; idx < HH * HH; idx += 512) {
        int m = idx >> 7, k = idx & 127;
        __nv_bfloat16 h, l; bsplit(w2g[idx], h, l);
        u32 o = (u32)m * SAB + (u32)k * 2u;
        *(__nv_bfloat16*)(sm + O_A2H + o) = h;
        *(__nv_bfloat16*)(sm + O_A2L + o) = l;
    }
    const float* xbase = g_xl + (size_t)b * HH * NN + p0;
    for (int idx = tid; idx < HH * NP; idx += 512) {
        int k = idx >> 7, n = idx & 127;
        __nv_bfloat16 h, l; bsplit(xbase[(size_t)k * NN + n], h, l);
        u32 o = (u32)n * SAB + (u32)k * 2u;
        *(__nv_bfloat16*)(sm + O_B1H + o) = h;
        *(__nv_bfloat16*)(sm + O_B1L + o) = l;
    }
    if (tid < HH) {
        *(float*)(sm + O_B1V + tid * 4) = l1b[blk * HH + tid] + g_hb[b * HH + tid];
        *(float*)(sm + O_B2V + tid * 4) = l2b[blk * HH + tid];
        *(float*)(sm + O_MK + tid * 4) = mask[(size_t)b * NN + p0 + tid];
    }
    if (last) {
        for (int idx = tid; idx < 3 * HH; idx += 512) *(float*)(sm + O_OW + idx * 4) = outw[idx];
        if (tid < 3) *(float*)(sm + O_OB + tid * 4) = outb[tid];
    }
    __syncthreads();

    // ---- stage 1 GEMM: D1 = W1x @ xl^T ----
    float acc[32];
    #pragma unroll
    for (int i = 0; i < 32; ++i) acc[i] = 0.f;
    gemm_ss(sb + O_A1H, sb + O_A1L, sb + O_B1H, sb + O_B1L, lane, m_base, n_base, acc);
    __syncthreads();   // all warps done reading A1 before B2 overwrites it

    // ---- epilogue 1: h = lrelu(D1 + b1 + hb) -> split into B2 ----
    int r = m_base + (lane >> 2);
    {
        float b1r  = *(const float*)(sm + O_B1V + r * 4);
        float b1r8 = *(const float*)(sm + O_B1V + (r + 8) * 4);
        #pragma unroll
        for (int nt = 0; nt < 8; ++nt) {
            int n0 = n_base + nt * 8 + 2 * (lane & 3);
            float v00 = lrelu(acc[nt * 4 + 0] + b1r);
            float v01 = lrelu(acc[nt * 4 + 1] + b1r);
            float v10 = lrelu(acc[nt * 4 + 2] + b1r8);
            float v11 = lrelu(acc[nt * 4 + 3] + b1r8);
            __nv_bfloat16 h, l;
            u32 o00 = (u32)n0 * SAB + (u32)r * 2u;
            u32 o01 = o00 + SAB;
            bsplit(v00, h, l);
            *(__nv_bfloat16*)(sm + O_B2H + o00) = h; *(__nv_bfloat16*)(sm + O_B2L + o00) = l;
            bsplit(v01, h, l);
            *(__nv_bfloat16*)(sm + O_B2H + o01) = h; *(__nv_bfloat16*)(sm + O_B2L + o01) = l;
            u32 o10 = o00 + 16u, o11 = o01 + 16u;  // row r+8
            bsplit(v10, h, l);
            *(__nv_bfloat16*)(sm + O_B2H + o10) = h; *(__nv_bfloat16*)(sm + O_B2L + o10) = l;
            bsplit(v11, h, l);
            *(__nv_bfloat16*)(sm + O_B2H + o11) = h; *(__nv_bfloat16*)(sm + O_B2L + o11) = l;
        }
    }
    __syncthreads();

    // ---- stage 2 GEMM: D2 = W2 @ h^T ----
    #pragma unroll
    for (int i = 0; i < 32; ++i) acc[i] = 0.f;
    gemm_ss(sb + O_A2H, sb + O_A2L, sb + O_B2H, sb + O_B2L, lane, m_base, n_base, acc);

    // ---- epilogue 2: xl_new = lrelu(D2 + b2 + xl) * mask ----
    float b2r  = *(const float*)(sm + O_B2V + r * 4);
    float b2r8 = *(const float*)(sm + O_B2V + (r + 8) * 4);
    float sumA = 0.f, sumB = 0.f;

    if (!last) {
        #pragma unroll
        for (int nt = 0; nt < 8; ++nt) {
            int n0 = n_base + nt * 8 + 2 * (lane & 3);
            float mk0 = *(const float*)(sm + O_MK + n0 * 4);
            float mk1 = *(const float*)(sm + O_MK + (n0 + 1) * 4);
            float* gr  = g_xl + ((size_t)(b * HH + r)) * NN + p0 + n0;
            float* gr8 = g_xl + ((size_t)(b * HH + r + 8)) * NN + p0 + n0;
            float2 ra = *(const float2*)gr;
            float2 rb = *(const float2*)gr8;
            float v0 = lrelu(acc[nt * 4 + 0] + b2r + ra.x) * mk0;
            float v1 = lrelu(acc[nt * 4 + 1] + b2r + ra.y) * mk1;
            float v2 = lrelu(acc[nt * 4 + 2] + b2r8 + rb.x) * mk0;
            float v3 = lrelu(acc[nt * 4 + 3] + b2r8 + rb.y) * mk1;
            *(float2*)gr  = make_float2(v0, v1);
            *(float2*)gr8 = make_float2(v2, v3);
            sumA += v0 + v1; sumB += v2 + v3;
        }
        #pragma unroll
        for (int o = 1; o <= 2; o <<= 1) {
            sumA += __shfl_xor_sync(0xffffffffu, sumA, o);
            sumB += __shfl_xor_sync(0xffffffffu, sumB, o);
        }
        if ((lane & 3) == 0) {
            int pc = b * NPART + tile * 2 + nh;
            g_part[pc * HH + r] = sumA;
            g_part[pc * HH + r + 8] = sumB;
        }
    } else {
        __syncthreads();   // done reading B2 before staging overwrite
        #pragma unroll
        for (int nt = 0; nt < 8; ++nt) {
            int n0 = n_base + nt * 8 + 2 * (lane & 3);
            float mk0 = *(const float*)(sm + O_MK + n0 * 4);
            float mk1 = *(const float*)(sm + O_MK + (n0 + 1) * 4);
            const float* gr  = g_xl + ((size_t)(b * HH + r)) * NN + p0 + n0;
            const float* gr8 = g_xl + ((size_t)(b * HH + r + 8)) * NN + p0 + n0;
            float2 ra = *(const float2*)gr;
            float2 rb = *(const float2*)gr8;
            float v0 = lrelu(acc[nt * 4 + 0] + b2r + ra.x) * mk0;
            float v1 = lrelu(acc[nt * 4 + 1] + b2r + ra.y) * mk1;
            float v2 = lrelu(acc[nt * 4 + 2] + b2r8 + rb.x) * mk0;
            float v3 = lrelu(acc[nt * 4 + 3] + b2r8 + rb.y) * mk1;
            *(float*)(sm + O_STG + ((u32)n0 * 129 + r) * 4)           = v0;
            *(float*)(sm + O_STG + ((u32)(n0 + 1) * 129 + r) * 4)     = v1;
            *(float*)(sm + O_STG + ((u32)n0 * 129 + r + 8) * 4)       = v2;
            *(float*)(sm + O_STG + ((u32)(n0 + 1) * 129 + r + 8) * 4) = v3;
        }
        __syncthreads();
        if (tid < NP) {
            int p = tid;
            float mk = *(const float*)(sm + O_MK + p * 4);
            float s0 = *(const float*)(sm + O_OB + 0);
            float s1 = *(const float*)(sm + O_OB + 4);
            float s2 = *(const float*)(sm + O_OB + 8);
            const float* row = (const float*)(sm + O_STG) + (u32)p * 129;
            for (int m = 0; m < HH; ++m) {
                float v = row[m];
                s0 = fmaf(v, *(const float*)(sm + O_OW + m * 4), s0);
                s1 = fmaf(v, *(const float*)(sm + O_OW + (HH + m) * 4), s1);
                s2 = fmaf(v, *(const float*)(sm + O_OW + (2 * HH + m) * 4), s2);
            }
            float* o = dout + ((size_t)b * NN + p0 + p) * 3;
            o[0] = mk * s0; o[1] = mk * s1; o[2] = mk * s2;
        }
    }
}

// ---------------------------------------------------------------------------
extern "C" void kernel_launch(void* const* d_in, const int* in_sizes, int n_in,
                              void* d_out, int out_size)
{
    const float* x_local = (const float*)d_in[0];
    const float* context = (const float*)d_in[1];
    const float* mask    = (const float*)d_in[2];
    const float* proj_lw = (const float*)d_in[3];
    const float* proj_lb = (const float*)d_in[4];
    const float* pg0w    = (const float*)d_in[5];
    const float* pg0b    = (const float*)d_in[6];
    const float* pg1w    = (const float*)d_in[7];
    const float* pg1b    = (const float*)d_in[8];
    const float* pg2w    = (const float*)d_in[9];
    const float* pg2b    = (const float*)d_in[10];
    const float* g1w     = (const float*)d_in[11];
    const float* g1b     = (const float*)d_in[12];
    const float* g2w     = (const float*)d_in[13];
    const float* g2b     = (const float*)d_in[14];
    const float* l1w     = (const float*)d_in[15];
    const float* l1b     = (const float*)d_in[16];
    const float* l2w     = (const float*)d_in[17];
    const float* l2b     = (const float*)d_in[18];
    const float* outw    = (const float*)d_in[19];
    const float* outb    = (const float*)d_in[20];
    float* out = (float*)d_out;

    cudaFuncSetAttribute(k_local, cudaFuncAttributeMaxDynamicSharedMemorySize, SMEM_SZ);

    k_proj<<<dim3(16, NT0), 256>>>(x_local, mask, proj_lw, proj_lb);
    for (int blk = 0; blk < NBLK; ++blk) {
        k_global<<<16, 128>>>(blk == 0 ? 0 : 1, blk, context,
                              pg0w, pg0b, pg1w, pg1b, pg2w, pg2b,
                              g1w, g1b, g2w, g2b, l1w);
        k_local<<<dim3(NT, 16), 512, SMEM_SZ>>>(
            blk, blk == NBLK - 1 ? 1 : 0,
            l1w, l1b, l2w, l2b, mask, outw, outb, out);
    }
}